// round 13
// baseline (speedup 1.0000x reference)
#include <cuda_runtime.h>
#include <cuda_fp16.h>
#include <math.h>

#define S_LEN   2048
#define DIMV    2048
#define KVD     512
#define NQH     16
#define NKVH    4
#define HDM     128
#define SCALE   0.08838834764831845f   // 1/sqrt(128)

// ---- scratch (no cudaMalloc allowed) ----
__device__ __half h_query[S_LEN * DIMV];
__device__ __half h_key[S_LEN * DIMV];
__device__ __half h_value[S_LEN * DIMV];
__device__ __half h_Wq[DIMV * DIMV];     // pre-scaled by SCALE
__device__ __half h_Wk[KVD * DIMV];
__device__ __half h_Wv[KVD * DIMV];
__device__ __half h_Wo[DIMV * DIMV];
__device__ __half g_Qh[S_LEN * DIMV];
__device__ __half g_Kh[S_LEN * KVD];
__device__ __half g_Vh[S_LEN * KVD];
__device__ __half g_Oh[S_LEN * DIMV];
__device__ float2 g_rope[S_LEN * 64];    // (cos, sin) table

// ============================================================
// helpers
// ============================================================
__device__ __forceinline__ void mma_f16(float* c, const unsigned* a, const unsigned* b) {
    asm volatile(
        "mma.sync.aligned.m16n8k16.row.col.f32.f16.f16.f32 "
        "{%0,%1,%2,%3}, {%4,%5,%6,%7}, {%8,%9}, {%0,%1,%2,%3};"
        : "+f"(c[0]), "+f"(c[1]), "+f"(c[2]), "+f"(c[3])
        : "r"(a[0]), "r"(a[1]), "r"(a[2]), "r"(a[3]), "r"(b[0]), "r"(b[1]));
}

__device__ __forceinline__ void ldsm_x4(
    unsigned& r0, unsigned& r1, unsigned& r2, unsigned& r3, unsigned addr)
{
    asm volatile("ldmatrix.sync.aligned.m8n8.x4.shared.b16 {%0,%1,%2,%3}, [%4];"
        : "=r"(r0), "=r"(r1), "=r"(r2), "=r"(r3) : "r"(addr));
}

__device__ __forceinline__ void ldsm_x4_t(
    unsigned& r0, unsigned& r1, unsigned& r2, unsigned& r3, unsigned addr)
{
    asm volatile("ldmatrix.sync.aligned.m8n8.x4.trans.shared.b16 {%0,%1,%2,%3}, [%4];"
        : "=r"(r0), "=r"(r1), "=r"(r2), "=r"(r3) : "r"(addr));
}

__device__ __forceinline__ void cp16(unsigned dst, const void* src) {
    asm volatile("cp.async.cg.shared.global [%0], [%1], 16;" :: "r"(dst), "l"(src));
}
__device__ __forceinline__ void cp_commit() {
    asm volatile("cp.async.commit_group;");
}
__device__ __forceinline__ void cp_wait0() {
    asm volatile("cp.async.wait_group 0;" ::: "memory");
}

// ============================================================
// fused fp32 -> fp16 convert of all inputs (Wq scaled by SCALE)
// ============================================================
#define N4_BIG ((S_LEN * DIMV) / 4)
#define N4_SM  ((KVD * DIMV) / 4)
#define N4_TOT (5 * N4_BIG + 2 * N4_SM)

__global__ void __launch_bounds__(256) cvt_all_kernel(
    const float4* __restrict__ q, const float4* __restrict__ k,
    const float4* __restrict__ v, const float4* __restrict__ wq,
    const float4* __restrict__ wo, const float4* __restrict__ wk,
    const float4* __restrict__ wv)
{
    int i = blockIdx.x * blockDim.x + threadIdx.x;
    if (i >= N4_TOT) return;
    const float4* src;
    __half2* dst;
    float s = 1.0f;
    int off;
    if (i < N4_BIG)           { src = q;  dst = (__half2*)h_query; off = i; }
    else if (i < 2 * N4_BIG)  { src = k;  dst = (__half2*)h_key;   off = i - N4_BIG; }
    else if (i < 3 * N4_BIG)  { src = v;  dst = (__half2*)h_value; off = i - 2 * N4_BIG; }
    else if (i < 4 * N4_BIG)  { src = wq; dst = (__half2*)h_Wq;    off = i - 3 * N4_BIG; s = SCALE; }
    else if (i < 5 * N4_BIG)  { src = wo; dst = (__half2*)h_Wo;    off = i - 4 * N4_BIG; }
    else if (i < 5 * N4_BIG + N4_SM) { src = wk; dst = (__half2*)h_Wk; off = i - 5 * N4_BIG; }
    else                      { src = wv; dst = (__half2*)h_Wv;    off = i - 5 * N4_BIG - N4_SM; }
    float4 val = src[off];
    dst[2 * off]     = __floats2half2_rn(val.x * s, val.y * s);
    dst[2 * off + 1] = __floats2half2_rn(val.z * s, val.w * s);
}

// ============================================================
// fp16 GEMM (R8 config — FROZEN):
// BM=128, BN=256, BK=64 halves, 3-stage cp.async, 256thr/8 warps,
// warp tile 64x64, mma.m16n8k16, ldmatrix. Smem stride 72 halves.
// ============================================================
#define GKH    2048
#define HSTR   72
#define GA_B   18432
#define GSTG_B 55296
#define G_SMEM (3 * GSTG_B)

__device__ __forceinline__ void g_issue_h(
    const __half* ag, const __half* bg, unsigned as_, unsigned bs_)
{
#pragma unroll
    for (int i = 0; i < 4; i++)
        cp16(as_ + i * 32 * HSTR * 2, ag + i * 32 * GKH);
#pragma unroll
    for (int i = 0; i < 8; i++)
        cp16(bs_ + i * 32 * HSTR * 2, bg + i * 32 * GKH);
    cp_commit();
}

template <bool HALF_OUT>
__device__ __forceinline__ void gemm_f16_body(
    const __half* __restrict__ A, const __half* __restrict__ B,
    const float* __restrict__ bias, float bscale, void* __restrict__ Cv,
    int N, int bm, int bn)
{
    extern __shared__ char smc[];
    unsigned smem_base = (unsigned)__cvta_generic_to_shared(smc);
    const int tid  = threadIdx.x;
    const int lane = tid & 31;
    const int wid  = tid >> 5;
    const int lg   = lane >> 2;
    const int lc   = lane & 3;
    const int wm   = (wid >> 2) * 64;
    const int wn   = (wid & 3) * 64;

    const int a_mrow = lane & 15, a_kseg = lane >> 4;
    const int b_nrow = ((lane >> 4) << 3) + (lane & 7);
    const int b_kseg = (lane >> 3) & 1;

    const int rowb = tid >> 3;
    const int seg  = tid & 7;

    const __half* Ag = A + (bm + rowb) * GKH + seg * 8;
    const __half* Bg = B + (bn + rowb) * GKH + seg * 8;
    const unsigned aoff = (rowb * HSTR + seg * 8) * 2;
    const unsigned boff = GA_B + (rowb * HSTR + seg * 8) * 2;

    float acc[4][8][4];
#pragma unroll
    for (int mt = 0; mt < 4; mt++)
#pragma unroll
        for (int nt = 0; nt < 8; nt++)
#pragma unroll
            for (int c = 0; c < 4; c++) acc[mt][nt][c] = 0.f;

    g_issue_h(Ag,      Bg,      smem_base + aoff,          smem_base + boff);
    g_issue_h(Ag + 64, Bg + 64, smem_base + GSTG_B + aoff, smem_base + GSTG_B + boff);

    const int nIter = GKH / 64;
    for (int kt = 0; kt < nIter; kt++) {
        asm volatile("cp.async.wait_group 1;" ::: "memory");
        __syncthreads();
        if (kt + 2 < nIter) {
            int s = (kt + 2) % 3;
            g_issue_h(Ag + (kt + 2) * 64, Bg + (kt + 2) * 64,
                      smem_base + s * GSTG_B + aoff,
                      smem_base + s * GSTG_B + boff);
        } else {
            cp_commit();
        }

        const unsigned As_b = smem_base + (kt % 3) * GSTG_B;
        const unsigned Bs_b = As_b + GA_B;
#pragma unroll
        for (int ks = 0; ks < 4; ks++) {
            unsigned af[4][4], bf[8][2];
#pragma unroll
            for (int mt = 0; mt < 4; mt++)
                ldsm_x4(af[mt][0], af[mt][1], af[mt][2], af[mt][3],
                        As_b + ((wm + mt * 16 + a_mrow) * HSTR + ks * 16 + a_kseg * 8) * 2);
#pragma unroll
            for (int np = 0; np < 4; np++)
                ldsm_x4(bf[2 * np][0], bf[2 * np][1], bf[2 * np + 1][0], bf[2 * np + 1][1],
                        Bs_b + ((wn + np * 16 + b_nrow) * HSTR + ks * 16 + b_kseg * 8) * 2);
#pragma unroll
            for (int mt = 0; mt < 4; mt++)
#pragma unroll
                for (int nt = 0; nt < 8; nt++)
                    mma_f16(acc[mt][nt], af[mt], bf[nt]);
        }
    }

#pragma unroll
    for (int mt = 0; mt < 4; mt++) {
        int row = bm + wm + mt * 16 + lg;
#pragma unroll
        for (int nt = 0; nt < 8; nt++) {
            int col = bn + wn + nt * 8 + 2 * lc;
            float b0 = __ldg(bias + col)     * bscale;
            float b1 = __ldg(bias + col + 1) * bscale;
            float o0 = acc[mt][nt][0] + b0, o1 = acc[mt][nt][1] + b1;
            float o2 = acc[mt][nt][2] + b0, o3 = acc[mt][nt][3] + b1;
            if (HALF_OUT) {
                __half* C = (__half*)Cv;
                *(__half2*)(C + row * N + col)       = __floats2half2_rn(o0, o1);
                *(__half2*)(C + (row + 8) * N + col) = __floats2half2_rn(o2, o3);
            } else {
                float* C = (float*)Cv;
                *(float2*)(C + row * N + col)       = make_float2(o0, o1);
                *(float2*)(C + (row + 8) * N + col) = make_float2(o2, o3);
            }
        }
    }
}

__global__ void __launch_bounds__(256) proj_kernel(
    const float* __restrict__ bq, const float* __restrict__ bk,
    const float* __restrict__ bv)
{
    int b = blockIdx.x;
    if (b < 128) {
        gemm_f16_body<true>(h_query, h_Wq, bq, SCALE, g_Qh, DIMV,
                            (b >> 3) * 128, (b & 7) * 256);
    } else if (b < 160) {
        int i = b - 128;
        gemm_f16_body<true>(h_key, h_Wk, bk, 1.0f, g_Kh, KVD,
                            (i >> 1) * 128, (i & 1) * 256);
    } else {
        int i = b - 160;
        gemm_f16_body<true>(h_value, h_Wv, bv, 1.0f, g_Vh, KVD,
                            (i >> 1) * 128, (i & 1) * 256);
    }
}

__global__ void __launch_bounds__(256) gemm_o_kernel(
    const float* __restrict__ bo, float* __restrict__ out)
{
    int b = blockIdx.x;
    gemm_f16_body<false>(g_Oh, h_Wo, bo, 1.0f, out, DIMV,
                         (b >> 3) * 128, (b & 7) * 256);
}

// ============================================================
// RoPE: table precompute + apply (R12 version)
// ============================================================
__global__ void __launch_bounds__(256) rope_tab_kernel()
{
    int idx = blockIdx.x * blockDim.x + threadIdx.x;
    if (idx >= S_LEN * 64) return;
    int j = idx & 63;
    int s = idx >> 6;
    float inv = powf(10000.0f, -(float)(2 * j) * (1.0f / 128.0f));
    float sn, cs;
    sincosf((float)s * inv, &sn, &cs);
    g_rope[idx] = make_float2(cs, sn);
}

__global__ void __launch_bounds__(256) rope_kernel()
{
    int idx = blockIdx.x * blockDim.x + threadIdx.x;   // s*32 + j2
    if (idx >= S_LEN * 32) return;
    int j2 = idx & 31;
    int s  = idx >> 5;
    float2 c0 = g_rope[s * 64 + 2 * j2];
    float2 c1 = g_rope[s * 64 + 2 * j2 + 1];

    __half2* qb = (__half2*)(g_Qh + s * DIMV);
#pragma unroll
    for (int hh = 0; hh < NQH; hh++) {
        float2 a = __half22float2(qb[hh * 64 + j2]);
        float2 b = __half22float2(qb[hh * 64 + 32 + j2]);
        qb[hh * 64 + j2]      = __floats2half2_rn(a.x * c0.x - b.x * c0.y,
                                                  a.y * c1.x - b.y * c1.y);
        qb[hh * 64 + 32 + j2] = __floats2half2_rn(b.x * c0.x + a.x * c0.y,
                                                  b.y * c1.x + a.y * c1.y);
    }
    __half2* kb = (__half2*)(g_Kh + s * KVD);
#pragma unroll
    for (int hh = 0; hh < NKVH; hh++) {
        float2 a = __half22float2(kb[hh * 64 + j2]);
        float2 b = __half22float2(kb[hh * 64 + 32 + j2]);
        kb[hh * 64 + j2]      = __floats2half2_rn(a.x * c0.x - b.x * c0.y,
                                                  a.y * c1.x - b.y * c1.y);
        kb[hh * 64 + 32 + j2] = __floats2half2_rn(b.x * c0.x + a.x * c0.y,
                                                  b.y * c1.x + a.y * c1.y);
    }
}

// ============================================================
// Flash attention, fp16 MMA + ldmatrix, causal GQA.
// BM=128, BN=64, HD=128, 256 thr / 8 warps, 1 CTA/SM.
// Halved iteration count + KV traffic vs BM=64.
// Smem (bytes):
//   [0, 34816)        Q (128x136 half), persistent
//   [34816, 69632)    K 2x (64x136 half)
//   [69632, 104448)   V 2x (64x136 half)
//   [104448, 139264)  sS f32 [128][68]
//   [139264, 157696)  sP half [128][72]
//   [157696, 159232)  stats m/l/esc (128 f32 each)
// ============================================================
#define AQ_B   0
#define AK_B   34816
#define AV_B   69632
#define ASS_B  104448
#define ASP_B  139264
#define AM_B   157696
#define AL_B   158208
#define AS_B   158720
#define ATT_SMEM 159232
#define KVSTR  136
#define PSH    72

__device__ __forceinline__ void attn_issue_kv(
    const __half* Kb, const __half* Vb, int j, int buf,
    unsigned smem_base, int tid)
{
    const __half* Ksrc = Kb + (j * 64) * KVD;
    const __half* Vsrc = Vb + (j * 64) * KVD;
    unsigned kb = smem_base + AK_B + buf * 17408;
    unsigned vb = smem_base + AV_B + buf * 17408;
#pragma unroll
    for (int i = 0; i < 4; i++) {
        int c   = tid + i * 256;
        int row = c >> 4;
        int sg  = c & 15;
        cp16(kb + (row * KVSTR + sg * 8) * 2, Ksrc + row * KVD + sg * 8);
        cp16(vb + (row * KVSTR + sg * 8) * 2, Vsrc + row * KVD + sg * 8);
    }
    cp_commit();
}

__global__ void __launch_bounds__(256) attn_kernel()
{
    extern __shared__ char smc[];
    unsigned smem_base = (unsigned)__cvta_generic_to_shared(smc);

    const int tid  = threadIdx.x;
    const int lane = tid & 31;
    const int wid  = tid >> 5;
    const int qt   = gridDim.x - 1 - blockIdx.x;   // heavy blocks first (q rows qt*128..+127)
    const int h    = blockIdx.y;
    const int kvh  = h >> 2;
    const int lg   = lane >> 2;
    const int lc   = lane & 3;

    const int a_mrow = lane & 15, a_kseg = lane >> 4;
    const int b_nrow = ((lane >> 4) << 3) + (lane & 7);
    const int b_kseg = (lane >> 3) & 1;

    // S warp tile 32x32: warps 4m x 2n
    const int wms = (wid >> 1) * 32;
    const int wns = (wid & 1) * 32;
    // PV warp tile 32x64: warps 4m x 2n
    const int wmp = (wid >> 1) * 32;
    const int wnp = (wid & 1) * 64;

    const __half* Qb = g_Qh + h * HDM;
    const __half* Kb = g_Kh + kvh * HDM;
    const __half* Vb = g_Vh + kvh * HDM;

    attn_issue_kv(Kb, Vb, 0, 0, smem_base, tid);

    // stage Q (128 x 128 halves, 136 stride)
    {
        const __half* Qsrc = Qb + (qt * 128) * DIMV;
#pragma unroll
        for (int i = 0; i < 8; i++) {
            int c   = tid + i * 256;     // 0..2047
            int row = c >> 4;
            int sg  = c & 15;
            cp16(smem_base + AQ_B + (row * KVSTR + sg * 8) * 2,
                 Qsrc + row * DIMV + sg * 8);
        }
        cp_commit();
    }
    {
        float* mrow = (float*)(smc + AM_B);
        float* lrow = (float*)(smc + AL_B);
        if (tid < 128) { mrow[tid] = -1e30f; lrow[tid] = 0.f; }
    }
    cp_wait0();
    __syncthreads();

    float oacc[2][8][4];
#pragma unroll
    for (int mt = 0; mt < 2; mt++)
#pragma unroll
        for (int nt = 0; nt < 8; nt++)
#pragma unroll
            for (int c = 0; c < 4; c++) oacc[mt][nt][c] = 0.f;

    const unsigned qbase = smem_base + AQ_B;
    const int jmax = 2 * qt + 1;
    int buf = 0;
    for (int j = 0; j <= jmax; j++) {
        if (j < jmax) attn_issue_kv(Kb, Vb, j + 1, buf ^ 1, smem_base, tid);

        // ---- S = Q K^T  (128x64, warp 32x32) ----
        const unsigned kbase = smem_base + AK_B + buf * 17408;
        float sacc[2][4][4];
#pragma unroll
        for (int mt = 0; mt < 2; mt++)
#pragma unroll
            for (int nt = 0; nt < 4; nt++)
#pragma unroll
                for (int c = 0; c < 4; c++) sacc[mt][nt][c] = 0.f;

#pragma unroll
        for (int ks = 0; ks < 8; ks++) {
            unsigned aq[2][4], bf[4][2];
#pragma unroll
            for (int mt = 0; mt < 2; mt++)
                ldsm_x4(aq[mt][0], aq[mt][1], aq[mt][2], aq[mt][3],
                        qbase + ((wms + mt * 16 + a_mrow) * KVSTR + ks * 16 + a_kseg * 8) * 2);
#pragma unroll
            for (int np = 0; np < 2; np++)
                ldsm_x4(bf[2 * np][0], bf[2 * np][1], bf[2 * np + 1][0], bf[2 * np + 1][1],
                        kbase + ((wns + np * 16 + b_nrow) * KVSTR + ks * 16 + b_kseg * 8) * 2);
#pragma unroll
            for (int mt = 0; mt < 2; mt++)
#pragma unroll
                for (int nt = 0; nt < 4; nt++)
                    mma_f16(sacc[mt][nt], aq[mt], bf[nt]);
        }

        float* sS = (float*)(smc + ASS_B);
#pragma unroll
        for (int mt = 0; mt < 2; mt++) {
            int r0 = wms + mt * 16 + lg;
#pragma unroll
            for (int nt = 0; nt < 4; nt++) {
                int c0 = wns + nt * 8 + 2 * lc;
                *(float2*)(sS + r0 * 68 + c0) =
                    make_float2(sacc[mt][nt][0], sacc[mt][nt][1]);
                *(float2*)(sS + (r0 + 8) * 68 + c0) =
                    make_float2(sacc[mt][nt][2], sacc[mt][nt][3]);
            }
        }
        __syncthreads();

        // ---- online softmax: 2 threads per row, 32 cols each ----
        {
            float* mrow = (float*)(smc + AM_B);
            float* lrow = (float*)(smc + AL_B);
            float* srow = (float*)(smc + AS_B);
            int row = tid >> 1;
            int q2  = tid & 1;
            float v[32];
#pragma unroll
            for (int w4 = 0; w4 < 8; w4++)
                *(float4*)(v + w4 * 4) =
                    *(const float4*)(sS + row * 68 + q2 * 32 + w4 * 4);
            if (j >= 2 * qt) {
                int grow = qt * 128 + row;
                int cbase = j * 64 + q2 * 32;
#pragma unroll
                for (int i = 0; i < 32; i++)
                    if (cbase + i > grow) v[i] = -1e30f;
            }
            float mo = mrow[row];
            float mx = v[0];
#pragma unroll
            for (int i = 1; i < 32; i++) mx = fmaxf(mx, v[i]);
            mx = fmaxf(mx, __shfl_xor_sync(0xffffffffu, mx, 1));
            float mnew = fmaxf(mo, mx);
            float sum = 0.f;
            unsigned pw[16];
#pragma unroll
            for (int i = 0; i < 16; i++) {
                float p0 = __expf(v[2 * i]     - mnew);
                float p1 = __expf(v[2 * i + 1] - mnew);
                sum += p0 + p1;
                __half2 hp = __floats2half2_rn(p0, p1);
                pw[i] = *(unsigned*)&hp;
            }
            sum += __shfl_xor_sync(0xffffffffu, sum, 1);
            unsigned* sPw = (unsigned*)(smc + ASP_B);
#pragma unroll
            for (int w4 = 0; w4 < 4; w4++)
                *(uint4*)(sPw + row * (PSH / 2) + q2 * 16 + w4 * 4) =
                    *(uint4*)(pw + w4 * 4);
            if (q2 == 0) {
                float esc = __expf(mo - mnew);
                mrow[row] = mnew;
                lrow[row] = lrow[row] * esc + sum;
                srow[row] = esc;
            }
        }
        __syncthreads();

        // ---- rescale O, then O += P V  (128x128, warp 32x64, k=64) ----
        {
            const float* srow = (const float*)(smc + AS_B);
#pragma unroll
            for (int mt = 0; mt < 2; mt++) {
                float e0 = srow[wmp + mt * 16 + lg];
                float e1 = srow[wmp + mt * 16 + lg + 8];
#pragma unroll
                for (int nt = 0; nt < 8; nt++) {
                    oacc[mt][nt][0] *= e0;
                    oacc[mt][nt][1] *= e0;
                    oacc[mt][nt][2] *= e1;
                    oacc[mt][nt][3] *= e1;
                }
            }
        }
        {
            const unsigned pbase = smem_base + ASP_B;
            const unsigned vbase = smem_base + AV_B + buf * 17408;
            const int seg = lane >> 3, r = lane & 7;
#pragma unroll
            for (int ks = 0; ks < 4; ks++) {
                unsigned af[2][4];
#pragma unroll
                for (int mt = 0; mt < 2; mt++)
                    ldsm_x4(af[mt][0], af[mt][1], af[mt][2], af[mt][3],
                            pbase + ((wmp + mt * 16 + a_mrow) * PSH + ks * 16 + a_kseg * 8) * 2);
                unsigned bv[8][2];
#pragma unroll
                for (int p = 0; p < 4; p++) {
                    int row = ks * 16 + (seg & 1) * 8 + r;
                    int col = wnp + p * 16 + (seg >> 1) * 8;
                    ldsm_x4_t(bv[2 * p][0], bv[2 * p][1],
                              bv[2 * p + 1][0], bv[2 * p + 1][1],
                              vbase + (row * KVSTR + col) * 2);
                }
#pragma unroll
                for (int mt = 0; mt < 2; mt++)
#pragma unroll
                    for (int nt = 0; nt < 8; nt++)
                        mma_f16(oacc[mt][nt], af[mt], bv[nt]);
            }
        }
        cp_wait0();
        __syncthreads();
        buf ^= 1;
    }

    // ---- epilogue ----
    {
        const float* lrow = (const float*)(smc + AL_B);
#pragma unroll
        for (int mt = 0; mt < 2; mt++) {
            int r  = wmp + mt * 16 + lg;
            float il0 = 1.0f / lrow[r];
            float il1 = 1.0f / lrow[r + 8];
            int gr = qt * 128 + r;
#pragma unroll
            for (int nt = 0; nt < 8; nt++) {
                int col = h * HDM + wnp + nt * 8 + 2 * lc;
                *(__half2*)(g_Oh + gr * DIMV + col) =
                    __floats2half2_rn(oacc[mt][nt][0] * il0, oacc[mt][nt][1] * il0);
                *(__half2*)(g_Oh + (gr + 8) * DIMV + col) =
                    __floats2half2_rn(oacc[mt][nt][2] * il1, oacc[mt][nt][3] * il1);
            }
        }
    }
}

// ============================================================
// launch
// ============================================================
extern "C" void kernel_launch(void* const* d_in, const int* in_sizes, int n_in,
                              void* d_out, int out_size)
{
    const float* query = (const float*)d_in[0];
    const float* key   = (const float*)d_in[1];
    const float* value = (const float*)d_in[2];
    const float* Wq    = (const float*)d_in[3];
    const float* bq    = (const float*)d_in[4];
    const float* Wk    = (const float*)d_in[5];
    const float* bk    = (const float*)d_in[6];
    const float* Wv    = (const float*)d_in[7];
    const float* bv    = (const float*)d_in[8];
    const float* Wo    = (const float*)d_in[9];
    const float* bo    = (const float*)d_in[10];
    float* out = (float*)d_out;

    cudaFuncSetAttribute((const void*)proj_kernel,
                         cudaFuncAttributeMaxDynamicSharedMemorySize, G_SMEM);
    cudaFuncSetAttribute((const void*)gemm_o_kernel,
                         cudaFuncAttributeMaxDynamicSharedMemorySize, G_SMEM);
    cudaFuncSetAttribute((const void*)attn_kernel,
                         cudaFuncAttributeMaxDynamicSharedMemorySize, ATT_SMEM);

    cvt_all_kernel<<<(N4_TOT + 255) / 256, 256>>>(
        (const float4*)query, (const float4*)key, (const float4*)value,
        (const float4*)Wq, (const float4*)Wo, (const float4*)Wk, (const float4*)Wv);

    rope_tab_kernel<<<(S_LEN * 64 + 255) / 256, 256>>>();

    proj_kernel<<<192, 256, G_SMEM>>>(bq, bk, bv);

    rope_kernel<<<(S_LEN * 32 + 255) / 256, 256>>>();

    attn_kernel<<<dim3(16, 16), 256, ATT_SMEM>>>();

    gemm_o_kernel<<<128, 256, G_SMEM>>>(bo, out);
}

// round 14
// speedup vs baseline: 1.0391x; 1.0391x over previous
#include <cuda_runtime.h>
#include <cuda_fp16.h>
#include <math.h>

#define S_LEN   2048
#define DIMV    2048
#define KVD     512
#define NQH     16
#define NKVH    4
#define HDM     128
#define SCALE   0.08838834764831845f   // 1/sqrt(128)

// ---- scratch (no cudaMalloc allowed) ----
__device__ __half h_query[S_LEN * DIMV];
__device__ __half h_key[S_LEN * DIMV];
__device__ __half h_value[S_LEN * DIMV];
__device__ __half h_Wq[DIMV * DIMV];     // pre-scaled by SCALE
__device__ __half h_Wk[KVD * DIMV];
__device__ __half h_Wv[KVD * DIMV];
__device__ __half h_Wo[DIMV * DIMV];
__device__ __half g_Qh[S_LEN * DIMV];
__device__ __half g_Kh[S_LEN * KVD];
__device__ __half g_Vh[S_LEN * KVD];
__device__ __half g_Oh[S_LEN * DIMV];
__device__ float2 g_rope[S_LEN * 64];    // (cos, sin) table

// ============================================================
// helpers
// ============================================================
__device__ __forceinline__ void mma_f16(float* c, const unsigned* a, const unsigned* b) {
    asm volatile(
        "mma.sync.aligned.m16n8k16.row.col.f32.f16.f16.f32 "
        "{%0,%1,%2,%3}, {%4,%5,%6,%7}, {%8,%9}, {%0,%1,%2,%3};"
        : "+f"(c[0]), "+f"(c[1]), "+f"(c[2]), "+f"(c[3])
        : "r"(a[0]), "r"(a[1]), "r"(a[2]), "r"(a[3]), "r"(b[0]), "r"(b[1]));
}

__device__ __forceinline__ void ldsm_x4(
    unsigned& r0, unsigned& r1, unsigned& r2, unsigned& r3, unsigned addr)
{
    asm volatile("ldmatrix.sync.aligned.m8n8.x4.shared.b16 {%0,%1,%2,%3}, [%4];"
        : "=r"(r0), "=r"(r1), "=r"(r2), "=r"(r3) : "r"(addr));
}

__device__ __forceinline__ void ldsm_x4_t(
    unsigned& r0, unsigned& r1, unsigned& r2, unsigned& r3, unsigned addr)
{
    asm volatile("ldmatrix.sync.aligned.m8n8.x4.trans.shared.b16 {%0,%1,%2,%3}, [%4];"
        : "=r"(r0), "=r"(r1), "=r"(r2), "=r"(r3) : "r"(addr));
}

__device__ __forceinline__ void cp16(unsigned dst, const void* src) {
    asm volatile("cp.async.cg.shared.global [%0], [%1], 16;" :: "r"(dst), "l"(src));
}
__device__ __forceinline__ void cp_commit() {
    asm volatile("cp.async.commit_group;");
}
__device__ __forceinline__ void cp_wait0() {
    asm volatile("cp.async.wait_group 0;" ::: "memory");
}

// ============================================================
// fused fp32 -> fp16 convert of all inputs (Wq scaled by SCALE)
// 4 independent float4 per thread (MLP=4) for DRAM-latency cover.
// ============================================================
#define N4_BIG ((S_LEN * DIMV) / 4)
#define N4_SM  ((KVD * DIMV) / 4)
#define N4_TOT (5 * N4_BIG + 2 * N4_SM)
#define CVT_THREADS ((N4_TOT + 3) / 4)

__device__ __forceinline__ void cvt_one(
    int i,
    const float4* __restrict__ q, const float4* __restrict__ k,
    const float4* __restrict__ v, const float4* __restrict__ wq,
    const float4* __restrict__ wo, const float4* __restrict__ wk,
    const float4* __restrict__ wv)
{
    const float4* src;
    __half2* dst;
    float s = 1.0f;
    int off;
    if (i < N4_BIG)           { src = q;  dst = (__half2*)h_query; off = i; }
    else if (i < 2 * N4_BIG)  { src = k;  dst = (__half2*)h_key;   off = i - N4_BIG; }
    else if (i < 3 * N4_BIG)  { src = v;  dst = (__half2*)h_value; off = i - 2 * N4_BIG; }
    else if (i < 4 * N4_BIG)  { src = wq; dst = (__half2*)h_Wq;    off = i - 3 * N4_BIG; s = SCALE; }
    else if (i < 5 * N4_BIG)  { src = wo; dst = (__half2*)h_Wo;    off = i - 4 * N4_BIG; }
    else if (i < 5 * N4_BIG + N4_SM) { src = wk; dst = (__half2*)h_Wk; off = i - 5 * N4_BIG; }
    else                      { src = wv; dst = (__half2*)h_Wv;    off = i - 5 * N4_BIG - N4_SM; }
    float4 val = __ldg(src + off);
    dst[2 * off]     = __floats2half2_rn(val.x * s, val.y * s);
    dst[2 * off + 1] = __floats2half2_rn(val.z * s, val.w * s);
}

__global__ void __launch_bounds__(256) cvt_all_kernel(
    const float4* __restrict__ q, const float4* __restrict__ k,
    const float4* __restrict__ v, const float4* __restrict__ wq,
    const float4* __restrict__ wo, const float4* __restrict__ wk,
    const float4* __restrict__ wv)
{
    int t = blockIdx.x * blockDim.x + threadIdx.x;
    int stride = gridDim.x * blockDim.x;
    // 4 strided elements per thread -> 4 loads in flight
#pragma unroll
    for (int r = 0; r < 4; r++) {
        int i = t + r * stride;
        if (i < N4_TOT)
            cvt_one(i, q, k, v, wq, wo, wk, wv);
    }
}

// ============================================================
// fp16 GEMM (R8 config — FROZEN):
// BM=128, BN=256, BK=64 halves, 3-stage cp.async, 256thr/8 warps,
// warp tile 64x64, mma.m16n8k16, ldmatrix. Smem stride 72 halves.
// ============================================================
#define GKH    2048
#define HSTR   72
#define GA_B   18432
#define GSTG_B 55296
#define G_SMEM (3 * GSTG_B)

__device__ __forceinline__ void g_issue_h(
    const __half* ag, const __half* bg, unsigned as_, unsigned bs_)
{
#pragma unroll
    for (int i = 0; i < 4; i++)
        cp16(as_ + i * 32 * HSTR * 2, ag + i * 32 * GKH);
#pragma unroll
    for (int i = 0; i < 8; i++)
        cp16(bs_ + i * 32 * HSTR * 2, bg + i * 32 * GKH);
    cp_commit();
}

template <bool HALF_OUT>
__device__ __forceinline__ void gemm_f16_body(
    const __half* __restrict__ A, const __half* __restrict__ B,
    const float* __restrict__ bias, float bscale, void* __restrict__ Cv,
    int N, int bm, int bn)
{
    extern __shared__ char smc[];
    unsigned smem_base = (unsigned)__cvta_generic_to_shared(smc);
    const int tid  = threadIdx.x;
    const int lane = tid & 31;
    const int wid  = tid >> 5;
    const int lg   = lane >> 2;
    const int lc   = lane & 3;
    const int wm   = (wid >> 2) * 64;
    const int wn   = (wid & 3) * 64;

    const int a_mrow = lane & 15, a_kseg = lane >> 4;
    const int b_nrow = ((lane >> 4) << 3) + (lane & 7);
    const int b_kseg = (lane >> 3) & 1;

    const int rowb = tid >> 3;
    const int seg  = tid & 7;

    const __half* Ag = A + (bm + rowb) * GKH + seg * 8;
    const __half* Bg = B + (bn + rowb) * GKH + seg * 8;
    const unsigned aoff = (rowb * HSTR + seg * 8) * 2;
    const unsigned boff = GA_B + (rowb * HSTR + seg * 8) * 2;

    float acc[4][8][4];
#pragma unroll
    for (int mt = 0; mt < 4; mt++)
#pragma unroll
        for (int nt = 0; nt < 8; nt++)
#pragma unroll
            for (int c = 0; c < 4; c++) acc[mt][nt][c] = 0.f;

    g_issue_h(Ag,      Bg,      smem_base + aoff,          smem_base + boff);
    g_issue_h(Ag + 64, Bg + 64, smem_base + GSTG_B + aoff, smem_base + GSTG_B + boff);

    const int nIter = GKH / 64;
    for (int kt = 0; kt < nIter; kt++) {
        asm volatile("cp.async.wait_group 1;" ::: "memory");
        __syncthreads();
        if (kt + 2 < nIter) {
            int s = (kt + 2) % 3;
            g_issue_h(Ag + (kt + 2) * 64, Bg + (kt + 2) * 64,
                      smem_base + s * GSTG_B + aoff,
                      smem_base + s * GSTG_B + boff);
        } else {
            cp_commit();
        }

        const unsigned As_b = smem_base + (kt % 3) * GSTG_B;
        const unsigned Bs_b = As_b + GA_B;
#pragma unroll
        for (int ks = 0; ks < 4; ks++) {
            unsigned af[4][4], bf[8][2];
#pragma unroll
            for (int mt = 0; mt < 4; mt++)
                ldsm_x4(af[mt][0], af[mt][1], af[mt][2], af[mt][3],
                        As_b + ((wm + mt * 16 + a_mrow) * HSTR + ks * 16 + a_kseg * 8) * 2);
#pragma unroll
            for (int np = 0; np < 4; np++)
                ldsm_x4(bf[2 * np][0], bf[2 * np][1], bf[2 * np + 1][0], bf[2 * np + 1][1],
                        Bs_b + ((wn + np * 16 + b_nrow) * HSTR + ks * 16 + b_kseg * 8) * 2);
#pragma unroll
            for (int mt = 0; mt < 4; mt++)
#pragma unroll
                for (int nt = 0; nt < 8; nt++)
                    mma_f16(acc[mt][nt], af[mt], bf[nt]);
        }
    }

#pragma unroll
    for (int mt = 0; mt < 4; mt++) {
        int row = bm + wm + mt * 16 + lg;
#pragma unroll
        for (int nt = 0; nt < 8; nt++) {
            int col = bn + wn + nt * 8 + 2 * lc;
            float b0 = __ldg(bias + col)     * bscale;
            float b1 = __ldg(bias + col + 1) * bscale;
            float o0 = acc[mt][nt][0] + b0, o1 = acc[mt][nt][1] + b1;
            float o2 = acc[mt][nt][2] + b0, o3 = acc[mt][nt][3] + b1;
            if (HALF_OUT) {
                __half* C = (__half*)Cv;
                *(__half2*)(C + row * N + col)       = __floats2half2_rn(o0, o1);
                *(__half2*)(C + (row + 8) * N + col) = __floats2half2_rn(o2, o3);
            } else {
                float* C = (float*)Cv;
                *(float2*)(C + row * N + col)       = make_float2(o0, o1);
                *(float2*)(C + (row + 8) * N + col) = make_float2(o2, o3);
            }
        }
    }
}

__global__ void __launch_bounds__(256) proj_kernel(
    const float* __restrict__ bq, const float* __restrict__ bk,
    const float* __restrict__ bv)
{
    int b = blockIdx.x;
    if (b < 128) {
        gemm_f16_body<true>(h_query, h_Wq, bq, SCALE, g_Qh, DIMV,
                            (b >> 3) * 128, (b & 7) * 256);
    } else if (b < 160) {
        int i = b - 128;
        gemm_f16_body<true>(h_key, h_Wk, bk, 1.0f, g_Kh, KVD,
                            (i >> 1) * 128, (i & 1) * 256);
    } else {
        int i = b - 160;
        gemm_f16_body<true>(h_value, h_Wv, bv, 1.0f, g_Vh, KVD,
                            (i >> 1) * 128, (i & 1) * 256);
    }
}

__global__ void __launch_bounds__(256) gemm_o_kernel(
    const float* __restrict__ bo, float* __restrict__ out)
{
    int b = blockIdx.x;
    gemm_f16_body<false>(g_Oh, h_Wo, bo, 1.0f, out, DIMV,
                         (b >> 3) * 128, (b & 7) * 256);
}

// ============================================================
// RoPE: table precompute + apply
// ============================================================
__global__ void __launch_bounds__(256) rope_tab_kernel()
{
    int idx = blockIdx.x * blockDim.x + threadIdx.x;
    if (idx >= S_LEN * 64) return;
    int j = idx & 63;
    int s = idx >> 6;
    float inv = powf(10000.0f, -(float)(2 * j) * (1.0f / 128.0f));
    float sn, cs;
    sincosf((float)s * inv, &sn, &cs);
    g_rope[idx] = make_float2(cs, sn);
}

__global__ void __launch_bounds__(256) rope_kernel()
{
    int idx = blockIdx.x * blockDim.x + threadIdx.x;   // s*32 + j2
    if (idx >= S_LEN * 32) return;
    int j2 = idx & 31;
    int s  = idx >> 5;
    float2 c0 = g_rope[s * 64 + 2 * j2];
    float2 c1 = g_rope[s * 64 + 2 * j2 + 1];

    __half2* qb = (__half2*)(g_Qh + s * DIMV);
#pragma unroll
    for (int hh = 0; hh < NQH; hh++) {
        float2 a = __half22float2(qb[hh * 64 + j2]);
        float2 b = __half22float2(qb[hh * 64 + 32 + j2]);
        qb[hh * 64 + j2]      = __floats2half2_rn(a.x * c0.x - b.x * c0.y,
                                                  a.y * c1.x - b.y * c1.y);
        qb[hh * 64 + 32 + j2] = __floats2half2_rn(b.x * c0.x + a.x * c0.y,
                                                  b.y * c1.x + a.y * c1.y);
    }
    __half2* kb = (__half2*)(g_Kh + s * KVD);
#pragma unroll
    for (int hh = 0; hh < NKVH; hh++) {
        float2 a = __half22float2(kb[hh * 64 + j2]);
        float2 b = __half22float2(kb[hh * 64 + 32 + j2]);
        kb[hh * 64 + j2]      = __floats2half2_rn(a.x * c0.x - b.x * c0.y,
                                                  a.y * c1.x - b.y * c1.y);
        kb[hh * 64 + 32 + j2] = __floats2half2_rn(b.x * c0.x + a.x * c0.y,
                                                  b.y * c1.x + a.y * c1.y);
    }
}

// ============================================================
// Flash attention (R12 config — FROZEN):
// fp16 MMA + ldmatrix, causal GQA, BM=BN=64, 256 thr, 2 CTAs/SM,
// Q frags streamed from persistent smem.
// ============================================================
#define AQ_B   0
#define AK_B   17408
#define AV_B   52224
#define ASS_B  87040
#define ASP_B  104448
#define AM_B   113664
#define AL_B   113920
#define AS_B   114176
#define ATT_SMEM 114432
#define KVSTR  136
#define PSH    72

__device__ __forceinline__ void attn_issue_kv(
    const __half* Kb, const __half* Vb, int j, int buf,
    unsigned smem_base, int tid)
{
    const __half* Ksrc = Kb + (j * 64) * KVD;
    const __half* Vsrc = Vb + (j * 64) * KVD;
    unsigned kb = smem_base + AK_B + buf * 17408;
    unsigned vb = smem_base + AV_B + buf * 17408;
#pragma unroll
    for (int i = 0; i < 4; i++) {
        int c   = tid + i * 256;
        int row = c >> 4;
        int sg  = c & 15;
        cp16(kb + (row * KVSTR + sg * 8) * 2, Ksrc + row * KVD + sg * 8);
        cp16(vb + (row * KVSTR + sg * 8) * 2, Vsrc + row * KVD + sg * 8);
    }
    cp_commit();
}

__global__ void __launch_bounds__(256, 2) attn_kernel()
{
    extern __shared__ char smc[];
    unsigned smem_base = (unsigned)__cvta_generic_to_shared(smc);

    const int tid  = threadIdx.x;
    const int lane = tid & 31;
    const int wid  = tid >> 5;
    const int qt   = gridDim.x - 1 - blockIdx.x;
    const int h    = blockIdx.y;
    const int kvh  = h >> 2;
    const int lg   = lane >> 2;
    const int lc   = lane & 3;

    const int a_mrow = lane & 15, a_kseg = lane >> 4;
    const int b_nrow = ((lane >> 4) << 3) + (lane & 7);
    const int b_kseg = (lane >> 3) & 1;

    const int wms = (wid >> 2) * 32;
    const int wns = (wid & 3) * 16;
    const int wmp = (wid >> 2) * 32;
    const int wnp = (wid & 3) * 32;

    const __half* Qb = g_Qh + h * HDM;
    const __half* Kb = g_Kh + kvh * HDM;
    const __half* Vb = g_Vh + kvh * HDM;

    attn_issue_kv(Kb, Vb, 0, 0, smem_base, tid);

    {
        const __half* Qsrc = Qb + (qt * 64) * DIMV;
#pragma unroll
        for (int i = 0; i < 4; i++) {
            int c   = tid + i * 256;
            int row = c >> 4;
            int sg  = c & 15;
            cp16(smem_base + AQ_B + (row * KVSTR + sg * 8) * 2,
                 Qsrc + row * DIMV + sg * 8);
        }
        cp_commit();
    }
    {
        float* mrow = (float*)(smc + AM_B);
        float* lrow = (float*)(smc + AL_B);
        if (tid < 64) { mrow[tid] = -1e30f; lrow[tid] = 0.f; }
    }
    cp_wait0();
    __syncthreads();

    float oacc[2][4][4];
#pragma unroll
    for (int mt = 0; mt < 2; mt++)
#pragma unroll
        for (int nt = 0; nt < 4; nt++)
#pragma unroll
            for (int c = 0; c < 4; c++) oacc[mt][nt][c] = 0.f;

    const unsigned qbase = smem_base + AQ_B;
    int buf = 0;
    for (int j = 0; j <= qt; j++) {
        if (j < qt) attn_issue_kv(Kb, Vb, j + 1, buf ^ 1, smem_base, tid);

        const unsigned kbase = smem_base + AK_B + buf * 17408;
        float sacc[2][2][4];
#pragma unroll
        for (int mt = 0; mt < 2; mt++)
#pragma unroll
            for (int nt = 0; nt < 2; nt++)
#pragma unroll
                for (int c = 0; c < 4; c++) sacc[mt][nt][c] = 0.f;

#pragma unroll
        for (int ks = 0; ks < 8; ks++) {
            unsigned aq[2][4], bf[2][2];
#pragma unroll
            for (int mt = 0; mt < 2; mt++)
                ldsm_x4(aq[mt][0], aq[mt][1], aq[mt][2], aq[mt][3],
                        qbase + ((wms + mt * 16 + a_mrow) * KVSTR + ks * 16 + a_kseg * 8) * 2);
            ldsm_x4(bf[0][0], bf[0][1], bf[1][0], bf[1][1],
                    kbase + ((wns + b_nrow) * KVSTR + ks * 16 + b_kseg * 8) * 2);
#pragma unroll
            for (int mt = 0; mt < 2; mt++)
#pragma unroll
                for (int nt = 0; nt < 2; nt++)
                    mma_f16(sacc[mt][nt], aq[mt], bf[nt]);
        }

        float* sS = (float*)(smc + ASS_B);
#pragma unroll
        for (int mt = 0; mt < 2; mt++) {
            int r0 = wms + mt * 16 + lg;
#pragma unroll
            for (int nt = 0; nt < 2; nt++) {
                int c0 = wns + nt * 8 + 2 * lc;
                *(float2*)(sS + r0 * 68 + c0) =
                    make_float2(sacc[mt][nt][0], sacc[mt][nt][1]);
                *(float2*)(sS + (r0 + 8) * 68 + c0) =
                    make_float2(sacc[mt][nt][2], sacc[mt][nt][3]);
            }
        }
        __syncthreads();

        {
            float* mrow = (float*)(smc + AM_B);
            float* lrow = (float*)(smc + AL_B);
            float* srow = (float*)(smc + AS_B);
            int row = tid >> 2;
            int q4  = tid & 3;
            float v[16];
            *(float4*)(v)      = *(const float4*)(sS + row * 68 + q4 * 16);
            *(float4*)(v + 4)  = *(const float4*)(sS + row * 68 + q4 * 16 + 4);
            *(float4*)(v + 8)  = *(const float4*)(sS + row * 68 + q4 * 16 + 8);
            *(float4*)(v + 12) = *(const float4*)(sS + row * 68 + q4 * 16 + 12);
            if (j == qt) {
#pragma unroll
                for (int i = 0; i < 16; i++)
                    if (q4 * 16 + i > row) v[i] = -1e30f;
            }
            float mo = mrow[row];
            float mx = v[0];
#pragma unroll
            for (int i = 1; i < 16; i++) mx = fmaxf(mx, v[i]);
            mx = fmaxf(mx, __shfl_xor_sync(0xffffffffu, mx, 1));
            mx = fmaxf(mx, __shfl_xor_sync(0xffffffffu, mx, 2));
            float mnew = fmaxf(mo, mx);
            float sum = 0.f;
            unsigned pw[8];
#pragma unroll
            for (int i = 0; i < 8; i++) {
                float p0 = __expf(v[2 * i]     - mnew);
                float p1 = __expf(v[2 * i + 1] - mnew);
                sum += p0 + p1;
                __half2 hp = __floats2half2_rn(p0, p1);
                pw[i] = *(unsigned*)&hp;
            }
            sum += __shfl_xor_sync(0xffffffffu, sum, 1);
            sum += __shfl_xor_sync(0xffffffffu, sum, 2);
            unsigned* sPw = (unsigned*)(smc + ASP_B);
            *(uint4*)(sPw + row * (PSH / 2) + q4 * 8)     = *(uint4*)(pw);
            *(uint4*)(sPw + row * (PSH / 2) + q4 * 8 + 4) = *(uint4*)(pw + 4);
            if (q4 == 0) {
                float esc = __expf(mo - mnew);
                mrow[row] = mnew;
                lrow[row] = lrow[row] * esc + sum;
                srow[row] = esc;
            }
        }
        __syncthreads();

        {
            const float* srow = (const float*)(smc + AS_B);
#pragma unroll
            for (int mt = 0; mt < 2; mt++) {
                float e0 = srow[wmp + mt * 16 + lg];
                float e1 = srow[wmp + mt * 16 + lg + 8];
#pragma unroll
                for (int nt = 0; nt < 4; nt++) {
                    oacc[mt][nt][0] *= e0;
                    oacc[mt][nt][1] *= e0;
                    oacc[mt][nt][2] *= e1;
                    oacc[mt][nt][3] *= e1;
                }
            }
        }
        {
            const unsigned pbase = smem_base + ASP_B;
            const unsigned vbase = smem_base + AV_B + buf * 17408;
            const int seg = lane >> 3, r = lane & 7;
#pragma unroll
            for (int ks = 0; ks < 4; ks++) {
                unsigned af[2][4];
#pragma unroll
                for (int mt = 0; mt < 2; mt++)
                    ldsm_x4(af[mt][0], af[mt][1], af[mt][2], af[mt][3],
                            pbase + ((wmp + mt * 16 + a_mrow) * PSH + ks * 16 + a_kseg * 8) * 2);
                unsigned bv[4][2];
#pragma unroll
                for (int p = 0; p < 2; p++) {
                    int row = ks * 16 + (seg & 1) * 8 + r;
                    int col = wnp + p * 16 + (seg >> 1) * 8;
                    ldsm_x4_t(bv[2 * p][0], bv[2 * p][1],
                              bv[2 * p + 1][0], bv[2 * p + 1][1],
                              vbase + (row * KVSTR + col) * 2);
                }
#pragma unroll
                for (int mt = 0; mt < 2; mt++)
#pragma unroll
                    for (int nt = 0; nt < 4; nt++)
                        mma_f16(oacc[mt][nt], af[mt], bv[nt]);
            }
        }
        cp_wait0();
        __syncthreads();
        buf ^= 1;
    }

    {
        const float* lrow = (const float*)(smc + AL_B);
#pragma unroll
        for (int mt = 0; mt < 2; mt++) {
            int r  = wmp + mt * 16 + lg;
            float il0 = 1.0f / lrow[r];
            float il1 = 1.0f / lrow[r + 8];
            int gr = qt * 64 + r;
#pragma unroll
            for (int nt = 0; nt < 4; nt++) {
                int col = h * HDM + wnp + nt * 8 + 2 * lc;
                *(__half2*)(g_Oh + gr * DIMV + col) =
                    __floats2half2_rn(oacc[mt][nt][0] * il0, oacc[mt][nt][1] * il0);
                *(__half2*)(g_Oh + (gr + 8) * DIMV + col) =
                    __floats2half2_rn(oacc[mt][nt][2] * il1, oacc[mt][nt][3] * il1);
            }
        }
    }
}

// ============================================================
// launch
// ============================================================
extern "C" void kernel_launch(void* const* d_in, const int* in_sizes, int n_in,
                              void* d_out, int out_size)
{
    const float* query = (const float*)d_in[0];
    const float* key   = (const float*)d_in[1];
    const float* value = (const float*)d_in[2];
    const float* Wq    = (const float*)d_in[3];
    const float* bq    = (const float*)d_in[4];
    const float* Wk    = (const float*)d_in[5];
    const float* bk    = (const float*)d_in[6];
    const float* Wv    = (const float*)d_in[7];
    const float* bv    = (const float*)d_in[8];
    const float* Wo    = (const float*)d_in[9];
    const float* bo    = (const float*)d_in[10];
    float* out = (float*)d_out;

    cudaFuncSetAttribute((const void*)proj_kernel,
                         cudaFuncAttributeMaxDynamicSharedMemorySize, G_SMEM);
    cudaFuncSetAttribute((const void*)gemm_o_kernel,
                         cudaFuncAttributeMaxDynamicSharedMemorySize, G_SMEM);
    cudaFuncSetAttribute((const void*)attn_kernel,
                         cudaFuncAttributeMaxDynamicSharedMemorySize, ATT_SMEM);

    cvt_all_kernel<<<(CVT_THREADS + 255) / 256, 256>>>(
        (const float4*)query, (const float4*)key, (const float4*)value,
        (const float4*)Wq, (const float4*)Wo, (const float4*)Wk, (const float4*)Wv);

    rope_tab_kernel<<<(S_LEN * 64 + 255) / 256, 256>>>();

    proj_kernel<<<192, 256, G_SMEM>>>(bq, bk, bv);

    rope_kernel<<<(S_LEN * 32 + 255) / 256, 256>>>();

    attn_kernel<<<dim3(32, 16), 256, ATT_SMEM>>>();

    gemm_o_kernel<<<128, 256, G_SMEM>>>(bo, out);
}

// round 16
// speedup vs baseline: 1.1858x; 1.1412x over previous
#include <cuda_runtime.h>
#include <cuda_fp16.h>
#include <math.h>

#define S_LEN   2048
#define DIMV    2048
#define KVD     512
#define NQH     16
#define NKVH    4
#define HDM     128
#define SCALE   0.08838834764831845f   // 1/sqrt(128)

// ---- scratch (no cudaMalloc allowed) ----
__device__ __half h_query[S_LEN * DIMV];
__device__ __half h_key[S_LEN * DIMV];
__device__ __half h_value[S_LEN * DIMV];
__device__ __half h_Wq[DIMV * DIMV];     // pre-scaled by SCALE
__device__ __half h_Wk[KVD * DIMV];
__device__ __half h_Wv[KVD * DIMV];
__device__ __half h_Wo[DIMV * DIMV];
__device__ __half g_Qh[S_LEN * DIMV];
__device__ __half g_Kh[S_LEN * KVD];
__device__ __half g_Vh[S_LEN * KVD];
__device__ __half g_Oh[S_LEN * DIMV];
__device__ float2 g_rope[S_LEN * 64];    // (cos, sin) table

// ============================================================
// helpers
// ============================================================
__device__ __forceinline__ void mma_f16(float* c, const unsigned* a, const unsigned* b) {
    asm volatile(
        "mma.sync.aligned.m16n8k16.row.col.f32.f16.f16.f32 "
        "{%0,%1,%2,%3}, {%4,%5,%6,%7}, {%8,%9}, {%0,%1,%2,%3};"
        : "+f"(c[0]), "+f"(c[1]), "+f"(c[2]), "+f"(c[3])
        : "r"(a[0]), "r"(a[1]), "r"(a[2]), "r"(a[3]), "r"(b[0]), "r"(b[1]));
}

__device__ __forceinline__ void ldsm_x4(
    unsigned& r0, unsigned& r1, unsigned& r2, unsigned& r3, unsigned addr)
{
    asm volatile("ldmatrix.sync.aligned.m8n8.x4.shared.b16 {%0,%1,%2,%3}, [%4];"
        : "=r"(r0), "=r"(r1), "=r"(r2), "=r"(r3) : "r"(addr));
}

__device__ __forceinline__ void ldsm_x4_t(
    unsigned& r0, unsigned& r1, unsigned& r2, unsigned& r3, unsigned addr)
{
    asm volatile("ldmatrix.sync.aligned.m8n8.x4.trans.shared.b16 {%0,%1,%2,%3}, [%4];"
        : "=r"(r0), "=r"(r1), "=r"(r2), "=r"(r3) : "r"(addr));
}

__device__ __forceinline__ void cp16(unsigned dst, const void* src) {
    asm volatile("cp.async.cg.shared.global [%0], [%1], 16;" :: "r"(dst), "l"(src));
}
__device__ __forceinline__ void cp_commit() {
    asm volatile("cp.async.commit_group;");
}
__device__ __forceinline__ void cp_wait0() {
    asm volatile("cp.async.wait_group 0;" ::: "memory");
}

// ============================================================
// fused fp32 -> fp16 convert of all inputs (Wq scaled by SCALE)
// ============================================================
#define N4_BIG ((S_LEN * DIMV) / 4)
#define N4_SM  ((KVD * DIMV) / 4)
#define N4_TOT (5 * N4_BIG + 2 * N4_SM)
#define CVT_THREADS ((N4_TOT + 3) / 4)

__device__ __forceinline__ void cvt_one(
    int i,
    const float4* __restrict__ q, const float4* __restrict__ k,
    const float4* __restrict__ v, const float4* __restrict__ wq,
    const float4* __restrict__ wo, const float4* __restrict__ wk,
    const float4* __restrict__ wv)
{
    const float4* src;
    __half2* dst;
    float s = 1.0f;
    int off;
    if (i < N4_BIG)           { src = q;  dst = (__half2*)h_query; off = i; }
    else if (i < 2 * N4_BIG)  { src = k;  dst = (__half2*)h_key;   off = i - N4_BIG; }
    else if (i < 3 * N4_BIG)  { src = v;  dst = (__half2*)h_value; off = i - 2 * N4_BIG; }
    else if (i < 4 * N4_BIG)  { src = wq; dst = (__half2*)h_Wq;    off = i - 3 * N4_BIG; s = SCALE; }
    else if (i < 5 * N4_BIG)  { src = wo; dst = (__half2*)h_Wo;    off = i - 4 * N4_BIG; }
    else if (i < 5 * N4_BIG + N4_SM) { src = wk; dst = (__half2*)h_Wk; off = i - 5 * N4_BIG; }
    else                      { src = wv; dst = (__half2*)h_Wv;    off = i - 5 * N4_BIG - N4_SM; }
    float4 val = __ldg(src + off);
    dst[2 * off]     = __floats2half2_rn(val.x * s, val.y * s);
    dst[2 * off + 1] = __floats2half2_rn(val.z * s, val.w * s);
}

__global__ void __launch_bounds__(256) cvt_all_kernel(
    const float4* __restrict__ q, const float4* __restrict__ k,
    const float4* __restrict__ v, const float4* __restrict__ wq,
    const float4* __restrict__ wo, const float4* __restrict__ wk,
    const float4* __restrict__ wv)
{
    int t = blockIdx.x * blockDim.x + threadIdx.x;
    int stride = gridDim.x * blockDim.x;
#pragma unroll
    for (int r = 0; r < 4; r++) {
        int i = t + r * stride;
        if (i < N4_TOT)
            cvt_one(i, q, k, v, wq, wo, wk, wv);
    }
}

// ============================================================
// fp16 GEMM (R8 config — FROZEN):
// BM=128, BN=256, BK=64 halves, 3-stage cp.async, 256thr/8 warps,
// warp tile 64x64, mma.m16n8k16, ldmatrix. Smem stride 72 halves.
// ============================================================
#define GKH    2048
#define HSTR   72
#define GA_B   18432
#define GSTG_B 55296
#define G_SMEM (3 * GSTG_B)

__device__ __forceinline__ void g_issue_h(
    const __half* ag, const __half* bg, unsigned as_, unsigned bs_)
{
#pragma unroll
    for (int i = 0; i < 4; i++)
        cp16(as_ + i * 32 * HSTR * 2, ag + i * 32 * GKH);
#pragma unroll
    for (int i = 0; i < 8; i++)
        cp16(bs_ + i * 32 * HSTR * 2, bg + i * 32 * GKH);
    cp_commit();
}

template <bool HALF_OUT>
__device__ __forceinline__ void gemm_f16_body(
    const __half* __restrict__ A, const __half* __restrict__ B,
    const float* __restrict__ bias, float bscale, void* __restrict__ Cv,
    int N, int bm, int bn)
{
    extern __shared__ char smc[];
    unsigned smem_base = (unsigned)__cvta_generic_to_shared(smc);
    const int tid  = threadIdx.x;
    const int lane = tid & 31;
    const int wid  = tid >> 5;
    const int lg   = lane >> 2;
    const int lc   = lane & 3;
    const int wm   = (wid >> 2) * 64;
    const int wn   = (wid & 3) * 64;

    const int a_mrow = lane & 15, a_kseg = lane >> 4;
    const int b_nrow = ((lane >> 4) << 3) + (lane & 7);
    const int b_kseg = (lane >> 3) & 1;

    const int rowb = tid >> 3;
    const int seg  = tid & 7;

    const __half* Ag = A + (bm + rowb) * GKH + seg * 8;
    const __half* Bg = B + (bn + rowb) * GKH + seg * 8;
    const unsigned aoff = (rowb * HSTR + seg * 8) * 2;
    const unsigned boff = GA_B + (rowb * HSTR + seg * 8) * 2;

    float acc[4][8][4];
#pragma unroll
    for (int mt = 0; mt < 4; mt++)
#pragma unroll
        for (int nt = 0; nt < 8; nt++)
#pragma unroll
            for (int c = 0; c < 4; c++) acc[mt][nt][c] = 0.f;

    g_issue_h(Ag,      Bg,      smem_base + aoff,          smem_base + boff);
    g_issue_h(Ag + 64, Bg + 64, smem_base + GSTG_B + aoff, smem_base + GSTG_B + boff);

    const int nIter = GKH / 64;
    for (int kt = 0; kt < nIter; kt++) {
        asm volatile("cp.async.wait_group 1;" ::: "memory");
        __syncthreads();
        if (kt + 2 < nIter) {
            int s = (kt + 2) % 3;
            g_issue_h(Ag + (kt + 2) * 64, Bg + (kt + 2) * 64,
                      smem_base + s * GSTG_B + aoff,
                      smem_base + s * GSTG_B + boff);
        } else {
            cp_commit();
        }

        const unsigned As_b = smem_base + (kt % 3) * GSTG_B;
        const unsigned Bs_b = As_b + GA_B;
#pragma unroll
        for (int ks = 0; ks < 4; ks++) {
            unsigned af[4][4], bf[8][2];
#pragma unroll
            for (int mt = 0; mt < 4; mt++)
                ldsm_x4(af[mt][0], af[mt][1], af[mt][2], af[mt][3],
                        As_b + ((wm + mt * 16 + a_mrow) * HSTR + ks * 16 + a_kseg * 8) * 2);
#pragma unroll
            for (int np = 0; np < 4; np++)
                ldsm_x4(bf[2 * np][0], bf[2 * np][1], bf[2 * np + 1][0], bf[2 * np + 1][1],
                        Bs_b + ((wn + np * 16 + b_nrow) * HSTR + ks * 16 + b_kseg * 8) * 2);
#pragma unroll
            for (int mt = 0; mt < 4; mt++)
#pragma unroll
                for (int nt = 0; nt < 8; nt++)
                    mma_f16(acc[mt][nt], af[mt], bf[nt]);
        }
    }

#pragma unroll
    for (int mt = 0; mt < 4; mt++) {
        int row = bm + wm + mt * 16 + lg;
#pragma unroll
        for (int nt = 0; nt < 8; nt++) {
            int col = bn + wn + nt * 8 + 2 * lc;
            float b0 = __ldg(bias + col)     * bscale;
            float b1 = __ldg(bias + col + 1) * bscale;
            float o0 = acc[mt][nt][0] + b0, o1 = acc[mt][nt][1] + b1;
            float o2 = acc[mt][nt][2] + b0, o3 = acc[mt][nt][3] + b1;
            if (HALF_OUT) {
                __half* C = (__half*)Cv;
                *(__half2*)(C + row * N + col)       = __floats2half2_rn(o0, o1);
                *(__half2*)(C + (row + 8) * N + col) = __floats2half2_rn(o2, o3);
            } else {
                float* C = (float*)Cv;
                *(float2*)(C + row * N + col)       = make_float2(o0, o1);
                *(float2*)(C + (row + 8) * N + col) = make_float2(o2, o3);
            }
        }
    }
}

__global__ void __launch_bounds__(256) proj_kernel(
    const float* __restrict__ bq, const float* __restrict__ bk,
    const float* __restrict__ bv)
{
    int b = blockIdx.x;
    if (b < 128) {
        gemm_f16_body<true>(h_query, h_Wq, bq, SCALE, g_Qh, DIMV,
                            (b >> 3) * 128, (b & 7) * 256);
    } else if (b < 160) {
        int i = b - 128;
        gemm_f16_body<true>(h_key, h_Wk, bk, 1.0f, g_Kh, KVD,
                            (i >> 1) * 128, (i & 1) * 256);
    } else {
        int i = b - 160;
        gemm_f16_body<true>(h_value, h_Wv, bv, 1.0f, g_Vh, KVD,
                            (i >> 1) * 128, (i & 1) * 256);
    }
}

__global__ void __launch_bounds__(256) gemm_o_kernel(
    const float* __restrict__ bo, float* __restrict__ out)
{
    int b = blockIdx.x;
    gemm_f16_body<false>(g_Oh, h_Wo, bo, 1.0f, out, DIMV,
                         (b >> 3) * 128, (b & 7) * 256);
}

// ============================================================
// RoPE: table precompute + apply
// ============================================================
__global__ void __launch_bounds__(256) rope_tab_kernel()
{
    int idx = blockIdx.x * blockDim.x + threadIdx.x;
    if (idx >= S_LEN * 64) return;
    int j = idx & 63;
    int s = idx >> 6;
    float inv = powf(10000.0f, -(float)(2 * j) * (1.0f / 128.0f));
    float sn, cs;
    sincosf((float)s * inv, &sn, &cs);
    g_rope[idx] = make_float2(cs, sn);
}

__global__ void __launch_bounds__(256) rope_kernel()
{
    int idx = blockIdx.x * blockDim.x + threadIdx.x;   // s*32 + j2
    if (idx >= S_LEN * 32) return;
    int j2 = idx & 31;
    int s  = idx >> 5;
    float2 c0 = g_rope[s * 64 + 2 * j2];
    float2 c1 = g_rope[s * 64 + 2 * j2 + 1];

    __half2* qb = (__half2*)(g_Qh + s * DIMV);
#pragma unroll
    for (int hh = 0; hh < NQH; hh++) {
        float2 a = __half22float2(qb[hh * 64 + j2]);
        float2 b = __half22float2(qb[hh * 64 + 32 + j2]);
        qb[hh * 64 + j2]      = __floats2half2_rn(a.x * c0.x - b.x * c0.y,
                                                  a.y * c1.x - b.y * c1.y);
        qb[hh * 64 + 32 + j2] = __floats2half2_rn(b.x * c0.x + a.x * c0.y,
                                                  b.y * c1.x + a.y * c1.y);
    }
    __half2* kb = (__half2*)(g_Kh + s * KVD);
#pragma unroll
    for (int hh = 0; hh < NKVH; hh++) {
        float2 a = __half22float2(kb[hh * 64 + j2]);
        float2 b = __half22float2(kb[hh * 64 + 32 + j2]);
        kb[hh * 64 + j2]      = __floats2half2_rn(a.x * c0.x - b.x * c0.y,
                                                  a.y * c1.x - b.y * c1.y);
        kb[hh * 64 + 32 + j2] = __floats2half2_rn(b.x * c0.x + a.x * c0.y,
                                                  b.y * c1.x + a.y * c1.y);
    }
}

// ============================================================
// Flash attention, FA2-style: warps split over M only.
// BM=64, BN=64, HD=128, 128 thr / 4 warps, 3 CTAs/SM.
// Per-warp: full S rows (16x64) -> softmax entirely in registers,
// P repacked in-register to PV A-fragments, m/l stats in regs.
// smem = K/V double buffers only (Q staged through K buf 1).
// ============================================================
#define AK_B   0
#define AV_B   34816
#define ATT_SMEM 69632
#define KVSTR  136

__device__ __forceinline__ void attn_issue_kv4(
    const __half* Kb, const __half* Vb, int j, int buf,
    unsigned smem_base, int tid)
{
    const __half* Ksrc = Kb + (j * 64) * KVD;
    const __half* Vsrc = Vb + (j * 64) * KVD;
    unsigned kb = smem_base + AK_B + buf * 17408;
    unsigned vb = smem_base + AV_B + buf * 17408;
#pragma unroll
    for (int i = 0; i < 8; i++) {
        int c   = tid + i * 128;
        int row = c >> 4;
        int sg  = c & 15;
        cp16(kb + (row * KVSTR + sg * 8) * 2, Ksrc + row * KVD + sg * 8);
        cp16(vb + (row * KVSTR + sg * 8) * 2, Vsrc + row * KVD + sg * 8);
    }
    cp_commit();
}

__global__ void __launch_bounds__(128, 3) attn_kernel()
{
    extern __shared__ char smc[];
    unsigned smem_base = (unsigned)__cvta_generic_to_shared(smc);

    const int tid  = threadIdx.x;
    const int lane = tid & 31;
    const int wid  = tid >> 5;          // 0..3, owns rows wid*16..+15
    const int qt   = gridDim.x - 1 - blockIdx.x;   // heavy blocks first
    const int h    = blockIdx.y;
    const int kvh  = h >> 2;
    const int lg   = lane >> 2;
    const int lc   = lane & 3;

    const int a_mrow = lane & 15, a_kseg = lane >> 4;
    const int b_nrow = ((lane >> 4) << 3) + (lane & 7);
    const int b_kseg = (lane >> 3) & 1;
    const int vseg = lane >> 3, vr = lane & 7;

    const __half* Qb = g_Qh + h * HDM;
    const __half* Kb = g_Kh + kvh * HDM;
    const __half* Vb = g_Vh + kvh * HDM;

    // stage Q into K buffer 1 (group 0)
    {
        const __half* Qsrc = Qb + (qt * 64) * DIMV;
#pragma unroll
        for (int i = 0; i < 8; i++) {
            int c   = tid + i * 128;
            int row = c >> 4;
            int sg  = c & 15;
            cp16(smem_base + AK_B + 17408 + (row * KVSTR + sg * 8) * 2,
                 Qsrc + row * DIMV + sg * 8);
        }
        cp_commit();
    }
    // K0/V0 into buf 0 (group 1)
    attn_issue_kv4(Kb, Vb, 0, 0, smem_base, tid);

    // wait Q (oldest group), extract fragments
    asm volatile("cp.async.wait_group 1;" ::: "memory");
    __syncthreads();
    unsigned qf[8][4];
#pragma unroll
    for (int ks = 0; ks < 8; ks++)
        ldsm_x4(qf[ks][0], qf[ks][1], qf[ks][2], qf[ks][3],
                smem_base + AK_B + 17408 +
                ((wid * 16 + a_mrow) * KVSTR + ks * 16 + a_kseg * 8) * 2);
    cp_wait0();
    __syncthreads();   // K0/V0 visible; Q staging area free for reuse

    float m0 = -1e30f, m1 = -1e30f, l0 = 0.f, l1 = 0.f;
    float oacc[16][4];
#pragma unroll
    for (int nt = 0; nt < 16; nt++)
#pragma unroll
        for (int c = 0; c < 4; c++) oacc[nt][c] = 0.f;

    int buf = 0;
    for (int j = 0; j <= qt; j++) {
        if (j < qt) attn_issue_kv4(Kb, Vb, j + 1, buf ^ 1, smem_base, tid);

        // ---- S = Q K^T : per-warp 16x64 ----
        const unsigned kbase = smem_base + AK_B + buf * 17408;
        float sacc[8][4];
#pragma unroll
        for (int nt = 0; nt < 8; nt++)
#pragma unroll
            for (int c = 0; c < 4; c++) sacc[nt][c] = 0.f;

#pragma unroll
        for (int ks = 0; ks < 8; ks++) {
            unsigned bf[8][2];
#pragma unroll
            for (int np = 0; np < 4; np++)
                ldsm_x4(bf[2 * np][0], bf[2 * np][1], bf[2 * np + 1][0], bf[2 * np + 1][1],
                        kbase + ((np * 16 + b_nrow) * KVSTR + ks * 16 + b_kseg * 8) * 2);
#pragma unroll
            for (int nt = 0; nt < 8; nt++)
                mma_f16(sacc[nt], qf[ks], bf[nt]);
        }

        // ---- causal mask (last tile only) ----
        if (j == qt) {
            int r0 = qt * 64 + wid * 16 + lg;
            int r1 = r0 + 8;
#pragma unroll
            for (int nt = 0; nt < 8; nt++) {
                int cb = j * 64 + nt * 8 + 2 * lc;
                if (cb     > r0) sacc[nt][0] = -1e30f;
                if (cb + 1 > r0) sacc[nt][1] = -1e30f;
                if (cb     > r1) sacc[nt][2] = -1e30f;
                if (cb + 1 > r1) sacc[nt][3] = -1e30f;
            }
        }

        // ---- in-register softmax (rows lg and lg+8) ----
        float mx0 = sacc[0][0], mx1 = sacc[0][2];
#pragma unroll
        for (int nt = 0; nt < 8; nt++) {
            mx0 = fmaxf(mx0, fmaxf(sacc[nt][0], sacc[nt][1]));
            mx1 = fmaxf(mx1, fmaxf(sacc[nt][2], sacc[nt][3]));
        }
        mx0 = fmaxf(mx0, __shfl_xor_sync(0xffffffffu, mx0, 1));
        mx0 = fmaxf(mx0, __shfl_xor_sync(0xffffffffu, mx0, 2));
        mx1 = fmaxf(mx1, __shfl_xor_sync(0xffffffffu, mx1, 1));
        mx1 = fmaxf(mx1, __shfl_xor_sync(0xffffffffu, mx1, 2));
        float mn0 = fmaxf(m0, mx0), mn1 = fmaxf(m1, mx1);
        float e0 = __expf(m0 - mn0), e1 = __expf(m1 - mn1);
        float s0 = 0.f, s1 = 0.f;
        unsigned pA[8], pB[8];
#pragma unroll
        for (int nt = 0; nt < 8; nt++) {
            float p00 = __expf(sacc[nt][0] - mn0);
            float p01 = __expf(sacc[nt][1] - mn0);
            float p10 = __expf(sacc[nt][2] - mn1);
            float p11 = __expf(sacc[nt][3] - mn1);
            s0 += p00 + p01;
            s1 += p10 + p11;
            __half2 hA = __floats2half2_rn(p00, p01);
            __half2 hB = __floats2half2_rn(p10, p11);
            pA[nt] = *(unsigned*)&hA;
            pB[nt] = *(unsigned*)&hB;
        }
        s0 += __shfl_xor_sync(0xffffffffu, s0, 1);
        s0 += __shfl_xor_sync(0xffffffffu, s0, 2);
        s1 += __shfl_xor_sync(0xffffffffu, s1, 1);
        s1 += __shfl_xor_sync(0xffffffffu, s1, 2);
        l0 = l0 * e0 + s0;  l1 = l1 * e1 + s1;
        m0 = mn0;  m1 = mn1;

        // ---- rescale O ----
#pragma unroll
        for (int nt = 0; nt < 16; nt++) {
            oacc[nt][0] *= e0;  oacc[nt][1] *= e0;
            oacc[nt][2] *= e1;  oacc[nt][3] *= e1;
        }

        // ---- O += P V : per-warp 16x128, k=64, P from registers ----
        const unsigned vbase = smem_base + AV_B + buf * 17408;
#pragma unroll
        for (int ks2 = 0; ks2 < 4; ks2++) {
            unsigned af[4] = { pA[2 * ks2], pB[2 * ks2], pA[2 * ks2 + 1], pB[2 * ks2 + 1] };
#pragma unroll
            for (int hf = 0; hf < 2; hf++) {
                unsigned bv[8][2];
#pragma unroll
                for (int p = 0; p < 4; p++) {
                    int pp = hf * 4 + p;
                    int row = ks2 * 16 + (vseg & 1) * 8 + vr;
                    int col = pp * 16 + (vseg >> 1) * 8;
                    ldsm_x4_t(bv[2 * p][0], bv[2 * p][1],
                              bv[2 * p + 1][0], bv[2 * p + 1][1],
                              vbase + (row * KVSTR + col) * 2);
                }
#pragma unroll
                for (int nt = 0; nt < 8; nt++)
                    mma_f16(oacc[hf * 8 + nt], af, bv[nt]);
            }
        }
        cp_wait0();
        __syncthreads();
        buf ^= 1;
    }

    // ---- epilogue ----
    {
        float il0 = 1.0f / l0, il1 = 1.0f / l1;
        int gr = qt * 64 + wid * 16 + lg;
#pragma unroll
        for (int nt = 0; nt < 16; nt++) {
            int col = h * HDM + nt * 8 + 2 * lc;
            *(__half2*)(g_Oh + gr * DIMV + col) =
                __floats2half2_rn(oacc[nt][0] * il0, oacc[nt][1] * il0);
            *(__half2*)(g_Oh + (gr + 8) * DIMV + col) =
                __floats2half2_rn(oacc[nt][2] * il1, oacc[nt][3] * il1);
        }
    }
}

// ============================================================
// launch
// ============================================================
extern "C" void kernel_launch(void* const* d_in, const int* in_sizes, int n_in,
                              void* d_out, int out_size)
{
    const float* query = (const float*)d_in[0];
    const float* key   = (const float*)d_in[1];
    const float* value = (const float*)d_in[2];
    const float* Wq    = (const float*)d_in[3];
    const float* bq    = (const float*)d_in[4];
    const float* Wk    = (const float*)d_in[5];
    const float* bk    = (const float*)d_in[6];
    const float* Wv    = (const float*)d_in[7];
    const float* bv    = (const float*)d_in[8];
    const float* Wo    = (const float*)d_in[9];
    const float* bo    = (const float*)d_in[10];
    float* out = (float*)d_out;

    cudaFuncSetAttribute((const void*)proj_kernel,
                         cudaFuncAttributeMaxDynamicSharedMemorySize, G_SMEM);
    cudaFuncSetAttribute((const void*)gemm_o_kernel,
                         cudaFuncAttributeMaxDynamicSharedMemorySize, G_SMEM);
    cudaFuncSetAttribute((const void*)attn_kernel,
                         cudaFuncAttributeMaxDynamicSharedMemorySize, ATT_SMEM);

    cvt_all_kernel<<<(CVT_THREADS + 255) / 256, 256>>>(
        (const float4*)query, (const float4*)key, (const float4*)value,
        (const float4*)Wq, (const float4*)Wo, (const float4*)Wk, (const float4*)Wv);

    rope_tab_kernel<<<(S_LEN * 64 + 255) / 256, 256>>>();

    proj_kernel<<<192, 256, G_SMEM>>>(bq, bk, bv);

    rope_kernel<<<(S_LEN * 32 + 255) / 256, 256>>>();

    attn_kernel<<<dim3(32, 16), 128, ATT_SMEM>>>();

    gemm_o_kernel<<<128, 256, G_SMEM>>>(bo, out);
}